// round 5
// baseline (speedup 1.0000x reference)
#include <cuda_runtime.h>
#include <cuda_bf16.h>
#include <cuda_fp16.h>
#include <math.h>
#include <stdint.h>

#define NN 50000
#define EE 800000
#define HID 128
#define LAYERS 4

// ---------------- device scratch ----------------
__device__ __align__(16) float g_xA[NN * HID];
__device__ __align__(16) float g_xB[NN * HID];
__device__ __align__(16) __half g_xlh[NN * HID];   // xl in fp16
__device__ __align__(16) float g_xr[NN * HID];
__device__ __align__(16) __nv_bfloat16 g_Wbhi[LAYERS * 256 * HID];
__device__ __align__(16) __nv_bfloat16 g_Wblo[LAYERS * 256 * HID];
__device__ float g_WembT[11 * HID];
__device__ int g_deg[NN];
__device__ int g_rowptr[NN + 1];
__device__ int g_next[NN];
__device__ __align__(16) int g_csrc[EE];
__device__ int g_part[256];
__device__ int g_poff[256];

// ---------------- prep ----------------
__global__ void k_prep(const float* __restrict__ Wemb,
                       const float* __restrict__ Wl,
                       const float* __restrict__ Wr,
                       float* __restrict__ out) {
    int t = blockIdx.x * blockDim.x + threadIdx.x;
    const int tot = LAYERS * 256 * HID;
    if (t < tot) {
        int l = t >> 15, r = t & 32767, row = r >> 7, k = r & 127;
        float v = (row < 128) ? Wl[(l << 14) + row * 128 + k]
                              : Wr[(l << 14) + (row - 128) * 128 + k];
        __nv_bfloat16 h = __float2bfloat16_rn(v);
        g_Wbhi[t] = h;
        g_Wblo[t] = __float2bfloat16_rn(v - __bfloat162float(h));
    }
    if (t < HID * 11) {
        int j = t / 11, k = t % 11;
        g_WembT[k * HID + j] = Wemb[t];
    }
    if (t < NN) g_deg[t] = 0;
    if (t < 256) out[t] = 0.f;
}

// ---------------- CSR build ----------------
__global__ void k_hist(const int* __restrict__ ei) {
    int e = blockIdx.x * blockDim.x + threadIdx.x;
    if (e < EE) atomicAdd(&g_deg[ei[EE + e]], 1);
}
__global__ void k_scan1() {
    __shared__ int sh[8];
    int b = blockIdx.x, t = threadIdx.x;
    int i = b * 256 + t;
    int v = (i < NN) ? g_deg[i] : 0;
#pragma unroll
    for (int o = 16; o; o >>= 1) v += __shfl_xor_sync(0xffffffffu, v, o);
    if ((t & 31) == 0) sh[t >> 5] = v;
    __syncthreads();
    if (t == 0) {
        int s = 0;
#pragma unroll
        for (int i2 = 0; i2 < 8; i2++) s += sh[i2];
        g_part[b] = s;
    }
}
__global__ void k_scan2(int nb) {
    __shared__ int wsum[8];
    int t = threadIdx.x;
    int v = (t < nb) ? g_part[t] : 0;
    int lane = t & 31, w = t >> 5;
    int x = v;
#pragma unroll
    for (int o = 1; o < 32; o <<= 1) {
        int y = __shfl_up_sync(0xffffffffu, x, o);
        if (lane >= o) x += y;
    }
    if (lane == 31) wsum[w] = x;
    __syncthreads();
    if (t == 0) {
        int run = 0;
#pragma unroll
        for (int i = 0; i < 8; i++) { int tmp = wsum[i]; wsum[i] = run; run += tmp; }
        g_rowptr[NN] = EE;
    }
    __syncthreads();
    g_poff[t] = x - v + wsum[w];
}
__global__ void k_scan3() {
    __shared__ int wsum[8];
    int b = blockIdx.x, t = threadIdx.x;
    int i = b * 256 + t;
    int v = (i < NN) ? g_deg[i] : 0;
    int lane = t & 31, w = t >> 5;
    int x = v;
#pragma unroll
    for (int o = 1; o < 32; o <<= 1) {
        int y = __shfl_up_sync(0xffffffffu, x, o);
        if (lane >= o) x += y;
    }
    if (lane == 31) wsum[w] = x;
    __syncthreads();
    if (t == 0) {
        int run = 0;
#pragma unroll
        for (int i2 = 0; i2 < 8; i2++) { int tmp = wsum[i2]; wsum[i2] = run; run += tmp; }
    }
    __syncthreads();
    int excl = x - v + wsum[w] + g_poff[b];
    if (i < NN) { g_rowptr[i] = excl; g_next[i] = excl; }
}
__global__ void k_scatter(const int* __restrict__ ei) {
    int e = blockIdx.x * blockDim.x + threadIdx.x;
    if (e < EE) {
        int d = ei[EE + e];
        int pos = atomicAdd(&g_next[d], 1);
        g_csrc[pos] = ei[e];
    }
}

// ---------------- embedding ----------------
__global__ void k_embed(const float* __restrict__ feat,
                        const float* __restrict__ bemb,
                        float* __restrict__ xout) {
    int gid = blockIdx.x * blockDim.x + threadIdx.x;
    if (gid >= NN * HID) return;
    int n = gid >> 7, j = gid & 127;
    float a = bemb[j];
#pragma unroll
    for (int k = 0; k < 11; k++) a += feat[n * 11 + k] * g_WembT[k * HID + j];
    xout[gid] = fmaxf(a, 0.f);
}

// ---------------- mma.sync bf16 split-precision GEMM ----------------
#define XROW 136

__device__ __forceinline__ void mma16816(float* d, uint32_t a0, uint32_t a1,
                                         uint32_t a2, uint32_t a3,
                                         uint32_t b0, uint32_t b1) {
    asm volatile(
        "mma.sync.aligned.m16n8k16.row.col.f32.bf16.bf16.f32 "
        "{%0,%1,%2,%3}, {%4,%5,%6,%7}, {%8,%9}, {%0,%1,%2,%3};"
        : "+f"(d[0]), "+f"(d[1]), "+f"(d[2]), "+f"(d[3])
        : "r"(a0), "r"(a1), "r"(a2), "r"(a3), "r"(b0), "r"(b1));
}

__global__ __launch_bounds__(256, 1) void k_gemm_mma(const float* __restrict__ xin,
                                                     const float* __restrict__ blp,
                                                     const float* __restrict__ brp,
                                                     const __nv_bfloat16* __restrict__ Whi,
                                                     const __nv_bfloat16* __restrict__ Wlo) {
    extern __shared__ __align__(16) char smem[];
    __nv_bfloat16* sxh = (__nv_bfloat16*)smem;
    __nv_bfloat16* sxl = (__nv_bfloat16*)(smem + 128 * XROW * 2);

    int tid = threadIdx.x;
    int n0 = blockIdx.x * 128;
    int side = blockIdx.y;
    const __nv_bfloat16* Wh = Whi + side * 128 * HID;
    const __nv_bfloat16* Wd = Wlo + side * 128 * HID;
    const float* bias = side ? brp : blp;

#pragma unroll
    for (int it = 0; it < 16; it++) {
        int idx = tid + it * 256;
        int row = idx >> 5, g4 = idx & 31;
        int n = n0 + row;
        float4 v = (n < NN) ? *(const float4*)&xin[n * HID + g4 * 4]
                            : make_float4(0.f, 0.f, 0.f, 0.f);
        __nv_bfloat162 h0 = __floats2bfloat162_rn(v.x, v.y);
        __nv_bfloat162 h1 = __floats2bfloat162_rn(v.z, v.w);
        __nv_bfloat162 l0 = __floats2bfloat162_rn(v.x - __bfloat162float(h0.x),
                                                  v.y - __bfloat162float(h0.y));
        __nv_bfloat162 l1 = __floats2bfloat162_rn(v.z - __bfloat162float(h1.x),
                                                  v.w - __bfloat162float(h1.y));
        uint32_t off = row * XROW + g4 * 4;
        *(uint2*)&sxh[off] = make_uint2(*(uint32_t*)&h0, *(uint32_t*)&h1);
        *(uint2*)&sxl[off] = make_uint2(*(uint32_t*)&l0, *(uint32_t*)&l1);
    }
    __syncthreads();

    int wid = tid >> 5, lane = tid & 31;
    int wm = wid & 3, wn = wid >> 2;
    int g = lane >> 2, tg = lane & 3;

    float acc[2][8][4];
#pragma unroll
    for (int mt = 0; mt < 2; mt++)
#pragma unroll
        for (int nt = 0; nt < 8; nt++)
#pragma unroll
            for (int q = 0; q < 4; q++) acc[mt][nt][q] = 0.f;

#pragma unroll
    for (int kk = 0; kk < 8; kk++) {
        int k0 = kk * 16;
        uint32_t ah[2][4], al[2][4];
#pragma unroll
        for (int mt = 0; mt < 2; mt++) {
            int rb = wm * 32 + mt * 16;
            uint32_t o0 = (rb + g) * XROW + k0 + tg * 2;
            uint32_t o1 = (rb + 8 + g) * XROW + k0 + tg * 2;
            ah[mt][0] = *(const uint32_t*)&sxh[o0];
            ah[mt][1] = *(const uint32_t*)&sxh[o1];
            ah[mt][2] = *(const uint32_t*)&sxh[o0 + 8];
            ah[mt][3] = *(const uint32_t*)&sxh[o1 + 8];
            al[mt][0] = *(const uint32_t*)&sxl[o0];
            al[mt][1] = *(const uint32_t*)&sxl[o1];
            al[mt][2] = *(const uint32_t*)&sxl[o0 + 8];
            al[mt][3] = *(const uint32_t*)&sxl[o1 + 8];
        }
#pragma unroll
        for (int half = 0; half < 2; half++) {
            uint32_t bh[4][2], bl[4][2];
#pragma unroll
            for (int q = 0; q < 4; q++) {
                int nt = half * 4 + q;
                int j = wn * 64 + nt * 8 + g;
                const __nv_bfloat16* ph = &Wh[j * HID + k0 + tg * 2];
                const __nv_bfloat16* pl = &Wd[j * HID + k0 + tg * 2];
                bh[q][0] = *(const uint32_t*)ph;
                bh[q][1] = *(const uint32_t*)(ph + 8);
                bl[q][0] = *(const uint32_t*)pl;
                bl[q][1] = *(const uint32_t*)(pl + 8);
            }
#pragma unroll
            for (int q = 0; q < 4; q++) {
                int nt = half * 4 + q;
#pragma unroll
                for (int mt = 0; mt < 2; mt++) {
                    mma16816(acc[mt][nt], ah[mt][0], ah[mt][1], ah[mt][2], ah[mt][3],
                             bh[q][0], bh[q][1]);
                    mma16816(acc[mt][nt], ah[mt][0], ah[mt][1], ah[mt][2], ah[mt][3],
                             bl[q][0], bl[q][1]);
                    mma16816(acc[mt][nt], al[mt][0], al[mt][1], al[mt][2], al[mt][3],
                             bh[q][0], bh[q][1]);
                }
            }
        }
    }

    // epilogue: bias + store (xl -> fp16, xr -> fp32)
    __half2* xlh2 = (__half2*)g_xlh;
#pragma unroll
    for (int mt = 0; mt < 2; mt++) {
        int rb = n0 + wm * 32 + mt * 16;
#pragma unroll
        for (int nt = 0; nt < 8; nt++) {
            int j = wn * 64 + nt * 8 + tg * 2;
            float2 bv = *(const float2*)&bias[j];
            int r0 = rb + g, r1 = rb + 8 + g;
            if (side == 0) {
                if (r0 < NN)
                    xlh2[r0 * 64 + (j >> 1)] =
                        __floats2half2_rn(acc[mt][nt][0] + bv.x, acc[mt][nt][1] + bv.y);
                if (r1 < NN)
                    xlh2[r1 * 64 + (j >> 1)] =
                        __floats2half2_rn(acc[mt][nt][2] + bv.x, acc[mt][nt][3] + bv.y);
            } else {
                if (r0 < NN)
                    *(float2*)&g_xr[r0 * HID + j] =
                        make_float2(acc[mt][nt][0] + bv.x, acc[mt][nt][1] + bv.y);
                if (r1 < NN)
                    *(float2*)&g_xr[r1 * HID + j] =
                        make_float2(acc[mt][nt][2] + bv.x, acc[mt][nt][3] + bv.y);
            }
        }
    }
}

// ---------------- edge aggregation: warp/dst, fp16 xl, 8-edge pipeline ----------------
__global__ void k_edge(const float* __restrict__ attL,
                       const float* __restrict__ biasL,
                       const float* __restrict__ xprev,
                       float* __restrict__ xout,
                       int add_res) {
    int wid = blockIdx.x * (blockDim.x >> 5) + (threadIdx.x >> 5);
    if (wid >= NN) return;
    int lane = threadIdx.x & 31;
    int h = lane >> 3;
    int col = h * 32 + (lane & 7) * 4;
    int hc = col >> 1;  // half2 index within row (64 half2 per row)
    int d = wid;

    const uint2* xl2 = (const uint2*)g_xlh;  // 8B = 4 halves per lane
    float4 xr4 = *(const float4*)&g_xr[d * HID + col];
    float4 a4 = *(const float4*)&attL[col];

    float s = 0.f;
    float ax = 0.f, ay = 0.f, az = 0.f, aw = 0.f;

    int beg = g_rowptr[d], end = g_rowptr[d + 1];
    int p = beg;

    for (; p + 8 <= end; p += 8) {
        int si[8];
#pragma unroll
        for (int j = 0; j < 8; j++) si[j] = g_csrc[p + j];
        uint2 uu[8];
#pragma unroll
        for (int j = 0; j < 8; j++) uu[j] = xl2[si[j] * 32 + (hc >> 1)];
        float4 vv[8];
        float rr[8];
#pragma unroll
        for (int j = 0; j < 8; j++) {
            float2 f0 = __half22float2(*(__half2*)&uu[j].x);
            float2 f1 = __half22float2(*(__half2*)&uu[j].y);
            vv[j] = make_float4(f0.x, f0.y, f1.x, f1.y);
            float e0 = vv[j].x + xr4.x; e0 = fmaxf(e0, 0.2f * e0);
            float e1 = vv[j].y + xr4.y; e1 = fmaxf(e1, 0.2f * e1);
            float e2 = vv[j].z + xr4.z; e2 = fmaxf(e2, 0.2f * e2);
            float e3 = vv[j].w + xr4.w; e3 = fmaxf(e3, 0.2f * e3);
            rr[j] = a4.x * e0 + a4.y * e1 + a4.z * e2 + a4.w * e3;
        }
#pragma unroll
        for (int j = 0; j < 8; j++) rr[j] += __shfl_xor_sync(0xffffffffu, rr[j], 1);
#pragma unroll
        for (int j = 0; j < 8; j++) rr[j] += __shfl_xor_sync(0xffffffffu, rr[j], 2);
#pragma unroll
        for (int j = 0; j < 8; j++) rr[j] += __shfl_xor_sync(0xffffffffu, rr[j], 4);
#pragma unroll
        for (int j = 0; j < 8; j++) {
            float pp = __expf(rr[j]);
            s += pp;
            ax += pp * vv[j].x; ay += pp * vv[j].y;
            az += pp * vv[j].z; aw += pp * vv[j].w;
        }
    }
    if (p + 4 <= end) {
        int si[4];
#pragma unroll
        for (int j = 0; j < 4; j++) si[j] = g_csrc[p + j];
        uint2 uu[4];
#pragma unroll
        for (int j = 0; j < 4; j++) uu[j] = xl2[si[j] * 32 + (hc >> 1)];
        float4 vv[4];
        float rr[4];
#pragma unroll
        for (int j = 0; j < 4; j++) {
            float2 f0 = __half22float2(*(__half2*)&uu[j].x);
            float2 f1 = __half22float2(*(__half2*)&uu[j].y);
            vv[j] = make_float4(f0.x, f0.y, f1.x, f1.y);
            float e0 = vv[j].x + xr4.x; e0 = fmaxf(e0, 0.2f * e0);
            float e1 = vv[j].y + xr4.y; e1 = fmaxf(e1, 0.2f * e1);
            float e2 = vv[j].z + xr4.z; e2 = fmaxf(e2, 0.2f * e2);
            float e3 = vv[j].w + xr4.w; e3 = fmaxf(e3, 0.2f * e3);
            rr[j] = a4.x * e0 + a4.y * e1 + a4.z * e2 + a4.w * e3;
        }
#pragma unroll
        for (int j = 0; j < 4; j++) rr[j] += __shfl_xor_sync(0xffffffffu, rr[j], 1);
#pragma unroll
        for (int j = 0; j < 4; j++) rr[j] += __shfl_xor_sync(0xffffffffu, rr[j], 2);
#pragma unroll
        for (int j = 0; j < 4; j++) rr[j] += __shfl_xor_sync(0xffffffffu, rr[j], 4);
#pragma unroll
        for (int j = 0; j < 4; j++) {
            float pp = __expf(rr[j]);
            s += pp;
            ax += pp * vv[j].x; ay += pp * vv[j].y;
            az += pp * vv[j].z; aw += pp * vv[j].w;
        }
        p += 4;
    }
    for (; p < end; p++) {
        int src = g_csrc[p];
        uint2 u = xl2[src * 32 + (hc >> 1)];
        float2 f0 = __half22float2(*(__half2*)&u.x);
        float2 f1 = __half22float2(*(__half2*)&u.y);
        float4 v = make_float4(f0.x, f0.y, f1.x, f1.y);
        float e0 = v.x + xr4.x; e0 = fmaxf(e0, 0.2f * e0);
        float e1 = v.y + xr4.y; e1 = fmaxf(e1, 0.2f * e1);
        float e2 = v.z + xr4.z; e2 = fmaxf(e2, 0.2f * e2);
        float e3 = v.w + xr4.w; e3 = fmaxf(e3, 0.2f * e3);
        float r = a4.x * e0 + a4.y * e1 + a4.z * e2 + a4.w * e3;
        r += __shfl_xor_sync(0xffffffffu, r, 1);
        r += __shfl_xor_sync(0xffffffffu, r, 2);
        r += __shfl_xor_sync(0xffffffffu, r, 4);
        float pp = __expf(r);
        s += pp;
        ax += pp * v.x; ay += pp * v.y; az += pp * v.z; aw += pp * v.w;
    }

    float inv = (s > 0.f) ? (1.f / s) : 0.f;
    float4 b4 = *(const float4*)&biasL[col];
    float o0 = fmaxf(ax * inv + b4.x, 0.f);
    float o1 = fmaxf(ay * inv + b4.y, 0.f);
    float o2 = fmaxf(az * inv + b4.z, 0.f);
    float o3 = fmaxf(aw * inv + b4.w, 0.f);
    if (add_res) {
        float4 rp = *(const float4*)&xprev[d * HID + col];
        o0 += rp.x; o1 += rp.y; o2 += rp.z; o3 += rp.w;
    }
    *(float4*)&xout[d * HID + col] = make_float4(o0, o1, o2, o3);
}

// ---------------- graph pooling ----------------
__global__ void k_reduce(const float* __restrict__ x, float* __restrict__ out) {
    int col = threadIdx.x & 127;
    int rg = threadIdx.x >> 7;
    float s = 0.f, mx = 0.f;
    for (int row = blockIdx.x * 2 + rg; row < NN; row += gridDim.x * 2) {
        float v = x[row * HID + col];
        s += v;
        mx = fmaxf(mx, v);
    }
    atomicAdd(&out[col], s);
    atomicMax((int*)&out[HID + col], __float_as_int(mx));
}
__global__ void k_scale(float* out) {
    int i = threadIdx.x;
    if (i < HID) out[i] *= (1.0f / (float)NN);
}

// ---------------- launch ----------------
extern "C" void kernel_launch(void* const* d_in, const int* in_sizes, int n_in,
                              void* d_out, int out_size) {
    const float* feat = (const float*)d_in[0];
    const int* ei = (const int*)d_in[1];
    int base = 2;
    if (n_in >= 11 || (n_in > 2 && in_sizes[2] == 1)) base = 3;
    const float* Wemb = (const float*)d_in[base + 0];
    const float* bemb = (const float*)d_in[base + 1];
    const float* Wl = (const float*)d_in[base + 2];
    const float* bl = (const float*)d_in[base + 3];
    const float* Wr = (const float*)d_in[base + 4];
    const float* br = (const float*)d_in[base + 5];
    const float* att = (const float*)d_in[base + 6];
    const float* bias = (const float*)d_in[base + 7];
    float* out = (float*)d_out;

    float *xA, *xB;
    cudaGetSymbolAddress((void**)&xA, g_xA);
    cudaGetSymbolAddress((void**)&xB, g_xB);
    __nv_bfloat16 *whi, *wlo;
    cudaGetSymbolAddress((void**)&whi, g_Wbhi);
    cudaGetSymbolAddress((void**)&wlo, g_Wblo);

    const int SMEM_GEMM = 128 * XROW * 2 * 2;
    cudaFuncSetAttribute(k_gemm_mma, cudaFuncAttributeMaxDynamicSharedMemorySize, SMEM_GEMM);

    float* xfinal = (out_size >= 256 + NN * HID) ? (out + 256) : xA;

    {
        int tot = LAYERS * 256 * HID;
        k_prep<<<(tot + 255) / 256, 256>>>(Wemb, Wl, Wr, out);
    }
    k_hist<<<(EE + 255) / 256, 256>>>(ei);
    const int NB = (NN + 255) / 256;
    k_scan1<<<NB, 256>>>();
    k_scan2<<<1, 256>>>(NB);
    k_scan3<<<NB, 256>>>();
    k_scatter<<<(EE + 255) / 256, 256>>>(ei);

    k_embed<<<(NN * HID + 255) / 256, 256>>>(feat, bemb, xA);

    const float* xin = xA;
    const int MT = (NN + 127) / 128;
    dim3 ggrid(MT, 2);
    for (int i = 0; i < LAYERS; i++) {
        k_gemm_mma<<<ggrid, 256, SMEM_GEMM>>>(xin, bl + i * HID, br + i * HID,
                                              whi + i * 256 * HID, wlo + i * 256 * HID);
        float* xo;
        if (i == 3) xo = xfinal;
        else xo = (i & 1) ? xA : xB;
        k_edge<<<(NN + 7) / 8, 256>>>(att + i * HID, bias + i * HID, xin, xo, (i > 0) ? 1 : 0);
        xin = xo;
    }

    k_reduce<<<512, 256>>>(xfinal, out);
    k_scale<<<1, 128>>>(out);
}

// round 6
// speedup vs baseline: 1.0912x; 1.0912x over previous
#include <cuda_runtime.h>
#include <cuda_bf16.h>
#include <cuda_fp16.h>
#include <math.h>
#include <stdint.h>

#define NN 50000
#define EE 800000
#define HID 128
#define LAYERS 4

// ---------------- device scratch ----------------
__device__ __align__(16) float g_xA[NN * HID];
__device__ __align__(16) float g_xB[NN * HID];
__device__ __align__(16) __half g_xlh[NN * HID];   // xl in fp16
__device__ __align__(16) float g_xr[NN * HID];
__device__ __align__(16) __nv_bfloat16 g_Wbhi[LAYERS * 256 * HID];
__device__ __align__(16) __nv_bfloat16 g_Wblo[LAYERS * 256 * HID];
__device__ float g_WembT[11 * HID];
__device__ int g_deg[NN];
__device__ int g_rowptr[NN + 1];
__device__ int g_next[NN];
__device__ __align__(16) int g_csrc[EE];
__device__ int g_part[256];
__device__ int g_poff[256];

// ---------------- prep ----------------
__global__ void k_prep(const float* __restrict__ Wemb,
                       const float* __restrict__ Wl,
                       const float* __restrict__ Wr,
                       float* __restrict__ out) {
    int t = blockIdx.x * blockDim.x + threadIdx.x;
    const int tot = LAYERS * 256 * HID;
    if (t < tot) {
        int l = t >> 15, r = t & 32767, row = r >> 7, k = r & 127;
        float v = (row < 128) ? Wl[(l << 14) + row * 128 + k]
                              : Wr[(l << 14) + (row - 128) * 128 + k];
        __nv_bfloat16 h = __float2bfloat16_rn(v);
        g_Wbhi[t] = h;
        g_Wblo[t] = __float2bfloat16_rn(v - __bfloat162float(h));
    }
    if (t < HID * 11) {
        int j = t / 11, k = t % 11;
        g_WembT[k * HID + j] = Wemb[t];
    }
    if (t < NN) g_deg[t] = 0;
    if (t < 256) out[t] = 0.f;
}

// ---------------- CSR build ----------------
__global__ void k_hist(const int* __restrict__ ei) {
    int e = blockIdx.x * blockDim.x + threadIdx.x;
    if (e < EE) atomicAdd(&g_deg[ei[EE + e]], 1);
}
__global__ void k_scan1() {
    __shared__ int sh[8];
    int b = blockIdx.x, t = threadIdx.x;
    int i = b * 256 + t;
    int v = (i < NN) ? g_deg[i] : 0;
#pragma unroll
    for (int o = 16; o; o >>= 1) v += __shfl_xor_sync(0xffffffffu, v, o);
    if ((t & 31) == 0) sh[t >> 5] = v;
    __syncthreads();
    if (t == 0) {
        int s = 0;
#pragma unroll
        for (int i2 = 0; i2 < 8; i2++) s += sh[i2];
        g_part[b] = s;
    }
}
__global__ void k_scan2(int nb) {
    __shared__ int wsum[8];
    int t = threadIdx.x;
    int v = (t < nb) ? g_part[t] : 0;
    int lane = t & 31, w = t >> 5;
    int x = v;
#pragma unroll
    for (int o = 1; o < 32; o <<= 1) {
        int y = __shfl_up_sync(0xffffffffu, x, o);
        if (lane >= o) x += y;
    }
    if (lane == 31) wsum[w] = x;
    __syncthreads();
    if (t == 0) {
        int run = 0;
#pragma unroll
        for (int i = 0; i < 8; i++) { int tmp = wsum[i]; wsum[i] = run; run += tmp; }
        g_rowptr[NN] = EE;
    }
    __syncthreads();
    g_poff[t] = x - v + wsum[w];
}
__global__ void k_scan3() {
    __shared__ int wsum[8];
    int b = blockIdx.x, t = threadIdx.x;
    int i = b * 256 + t;
    int v = (i < NN) ? g_deg[i] : 0;
    int lane = t & 31, w = t >> 5;
    int x = v;
#pragma unroll
    for (int o = 1; o < 32; o <<= 1) {
        int y = __shfl_up_sync(0xffffffffu, x, o);
        if (lane >= o) x += y;
    }
    if (lane == 31) wsum[w] = x;
    __syncthreads();
    if (t == 0) {
        int run = 0;
#pragma unroll
        for (int i2 = 0; i2 < 8; i2++) { int tmp = wsum[i2]; wsum[i2] = run; run += tmp; }
    }
    __syncthreads();
    int excl = x - v + wsum[w] + g_poff[b];
    if (i < NN) { g_rowptr[i] = excl; g_next[i] = excl; }
}
__global__ void k_scatter(const int* __restrict__ ei) {
    int e = blockIdx.x * blockDim.x + threadIdx.x;
    if (e < EE) {
        int d = ei[EE + e];
        int pos = atomicAdd(&g_next[d], 1);
        g_csrc[pos] = ei[e];
    }
}

// ---------------- embedding ----------------
__global__ void k_embed(const float* __restrict__ feat,
                        const float* __restrict__ bemb,
                        float* __restrict__ xout) {
    int gid = blockIdx.x * blockDim.x + threadIdx.x;
    if (gid >= NN * HID) return;
    int n = gid >> 7, j = gid & 127;
    float a = bemb[j];
#pragma unroll
    for (int k = 0; k < 11; k++) a += feat[n * 11 + k] * g_WembT[k * HID + j];
    xout[gid] = fmaxf(a, 0.f);
}

// ---------------- mma.sync bf16 split-precision GEMM ----------------
#define XROW 136

__device__ __forceinline__ void mma16816(float* d, uint32_t a0, uint32_t a1,
                                         uint32_t a2, uint32_t a3,
                                         uint32_t b0, uint32_t b1) {
    asm volatile(
        "mma.sync.aligned.m16n8k16.row.col.f32.bf16.bf16.f32 "
        "{%0,%1,%2,%3}, {%4,%5,%6,%7}, {%8,%9}, {%0,%1,%2,%3};"
        : "+f"(d[0]), "+f"(d[1]), "+f"(d[2]), "+f"(d[3])
        : "r"(a0), "r"(a1), "r"(a2), "r"(a3), "r"(b0), "r"(b1));
}

__global__ __launch_bounds__(256, 1) void k_gemm_mma(const float* __restrict__ xin,
                                                     const float* __restrict__ blp,
                                                     const float* __restrict__ brp,
                                                     const __nv_bfloat16* __restrict__ Whi,
                                                     const __nv_bfloat16* __restrict__ Wlo) {
    extern __shared__ __align__(16) char smem[];
    __nv_bfloat16* sxh = (__nv_bfloat16*)smem;
    __nv_bfloat16* sxl = (__nv_bfloat16*)(smem + 128 * XROW * 2);

    int tid = threadIdx.x;
    int n0 = blockIdx.x * 128;
    int side = blockIdx.y;
    const __nv_bfloat16* Wh = Whi + side * 128 * HID;
    const __nv_bfloat16* Wd = Wlo + side * 128 * HID;
    const float* bias = side ? brp : blp;

#pragma unroll
    for (int it = 0; it < 16; it++) {
        int idx = tid + it * 256;
        int row = idx >> 5, g4 = idx & 31;
        int n = n0 + row;
        float4 v = (n < NN) ? *(const float4*)&xin[n * HID + g4 * 4]
                            : make_float4(0.f, 0.f, 0.f, 0.f);
        __nv_bfloat162 h0 = __floats2bfloat162_rn(v.x, v.y);
        __nv_bfloat162 h1 = __floats2bfloat162_rn(v.z, v.w);
        __nv_bfloat162 l0 = __floats2bfloat162_rn(v.x - __bfloat162float(h0.x),
                                                  v.y - __bfloat162float(h0.y));
        __nv_bfloat162 l1 = __floats2bfloat162_rn(v.z - __bfloat162float(h1.x),
                                                  v.w - __bfloat162float(h1.y));
        uint32_t off = row * XROW + g4 * 4;
        *(uint2*)&sxh[off] = make_uint2(*(uint32_t*)&h0, *(uint32_t*)&h1);
        *(uint2*)&sxl[off] = make_uint2(*(uint32_t*)&l0, *(uint32_t*)&l1);
    }
    __syncthreads();

    int wid = tid >> 5, lane = tid & 31;
    int wm = wid & 3, wn = wid >> 2;
    int g = lane >> 2, tg = lane & 3;

    float acc[2][8][4];
#pragma unroll
    for (int mt = 0; mt < 2; mt++)
#pragma unroll
        for (int nt = 0; nt < 8; nt++)
#pragma unroll
            for (int q = 0; q < 4; q++) acc[mt][nt][q] = 0.f;

#pragma unroll
    for (int kk = 0; kk < 8; kk++) {
        int k0 = kk * 16;
        uint32_t ah[2][4], al[2][4];
#pragma unroll
        for (int mt = 0; mt < 2; mt++) {
            int rb = wm * 32 + mt * 16;
            uint32_t o0 = (rb + g) * XROW + k0 + tg * 2;
            uint32_t o1 = (rb + 8 + g) * XROW + k0 + tg * 2;
            ah[mt][0] = *(const uint32_t*)&sxh[o0];
            ah[mt][1] = *(const uint32_t*)&sxh[o1];
            ah[mt][2] = *(const uint32_t*)&sxh[o0 + 8];
            ah[mt][3] = *(const uint32_t*)&sxh[o1 + 8];
            al[mt][0] = *(const uint32_t*)&sxl[o0];
            al[mt][1] = *(const uint32_t*)&sxl[o1];
            al[mt][2] = *(const uint32_t*)&sxl[o0 + 8];
            al[mt][3] = *(const uint32_t*)&sxl[o1 + 8];
        }
#pragma unroll
        for (int half = 0; half < 2; half++) {
            uint32_t bh[4][2], bl[4][2];
#pragma unroll
            for (int q = 0; q < 4; q++) {
                int nt = half * 4 + q;
                int j = wn * 64 + nt * 8 + g;
                const __nv_bfloat16* ph = &Wh[j * HID + k0 + tg * 2];
                const __nv_bfloat16* pl = &Wd[j * HID + k0 + tg * 2];
                bh[q][0] = *(const uint32_t*)ph;
                bh[q][1] = *(const uint32_t*)(ph + 8);
                bl[q][0] = *(const uint32_t*)pl;
                bl[q][1] = *(const uint32_t*)(pl + 8);
            }
#pragma unroll
            for (int q = 0; q < 4; q++) {
                int nt = half * 4 + q;
#pragma unroll
                for (int mt = 0; mt < 2; mt++) {
                    mma16816(acc[mt][nt], ah[mt][0], ah[mt][1], ah[mt][2], ah[mt][3],
                             bh[q][0], bh[q][1]);
                    mma16816(acc[mt][nt], ah[mt][0], ah[mt][1], ah[mt][2], ah[mt][3],
                             bl[q][0], bl[q][1]);
                    mma16816(acc[mt][nt], al[mt][0], al[mt][1], al[mt][2], al[mt][3],
                             bh[q][0], bh[q][1]);
                }
            }
        }
    }

    // epilogue: bias + store (xl -> fp16, xr -> fp32)
    __half2* xlh2 = (__half2*)g_xlh;
#pragma unroll
    for (int mt = 0; mt < 2; mt++) {
        int rb = n0 + wm * 32 + mt * 16;
#pragma unroll
        for (int nt = 0; nt < 8; nt++) {
            int j = wn * 64 + nt * 8 + tg * 2;
            float2 bv = *(const float2*)&bias[j];
            int r0 = rb + g, r1 = rb + 8 + g;
            if (side == 0) {
                if (r0 < NN)
                    xlh2[r0 * 64 + (j >> 1)] =
                        __floats2half2_rn(acc[mt][nt][0] + bv.x, acc[mt][nt][1] + bv.y);
                if (r1 < NN)
                    xlh2[r1 * 64 + (j >> 1)] =
                        __floats2half2_rn(acc[mt][nt][2] + bv.x, acc[mt][nt][3] + bv.y);
            } else {
                if (r0 < NN)
                    *(float2*)&g_xr[r0 * HID + j] =
                        make_float2(acc[mt][nt][0] + bv.x, acc[mt][nt][1] + bv.y);
                if (r1 < NN)
                    *(float2*)&g_xr[r1 * HID + j] =
                        make_float2(acc[mt][nt][2] + bv.x, acc[mt][nt][3] + bv.y);
            }
        }
    }
}

// ---------------- edge aggregation: warp/dst, fp16 xl, 4-edge unroll ----------------
__global__ void k_edge(const float* __restrict__ attL,
                       const float* __restrict__ biasL,
                       const float* __restrict__ xprev,
                       float* __restrict__ xout,
                       int add_res) {
    int wid = blockIdx.x * (blockDim.x >> 5) + (threadIdx.x >> 5);
    if (wid >= NN) return;
    int lane = threadIdx.x & 31;
    int h = lane >> 3;
    int col = h * 32 + (lane & 7) * 4;
    int qc = col >> 2;  // uint2 (4-half) index within row: 32 per row
    int d = wid;

    const uint2* xl2 = (const uint2*)g_xlh;
    float4 xr4 = *(const float4*)&g_xr[d * HID + col];
    float4 a4 = *(const float4*)&attL[col];

    float s = 0.f;
    float ax = 0.f, ay = 0.f, az = 0.f, aw = 0.f;

    int beg = g_rowptr[d], end = g_rowptr[d + 1];
    int p = beg;
    for (; p < end && (p & 3); p++) {
        int src = g_csrc[p];
        uint2 u = xl2[src * 32 + qc];
        float2 f0 = __half22float2(*(__half2*)&u.x);
        float2 f1 = __half22float2(*(__half2*)&u.y);
        float4 v = make_float4(f0.x, f0.y, f1.x, f1.y);
        float e0 = v.x + xr4.x; e0 = fmaxf(e0, 0.2f * e0);
        float e1 = v.y + xr4.y; e1 = fmaxf(e1, 0.2f * e1);
        float e2 = v.z + xr4.z; e2 = fmaxf(e2, 0.2f * e2);
        float e3 = v.w + xr4.w; e3 = fmaxf(e3, 0.2f * e3);
        float r = a4.x * e0 + a4.y * e1 + a4.z * e2 + a4.w * e3;
        r += __shfl_xor_sync(0xffffffffu, r, 1);
        r += __shfl_xor_sync(0xffffffffu, r, 2);
        r += __shfl_xor_sync(0xffffffffu, r, 4);
        float pp = __expf(r);
        s += pp;
        ax += pp * v.x; ay += pp * v.y; az += pp * v.z; aw += pp * v.w;
    }
    for (; p + 4 <= end; p += 4) {
        int4 s4 = *(const int4*)&g_csrc[p];
        uint2 uu[4];
        uu[0] = xl2[s4.x * 32 + qc];
        uu[1] = xl2[s4.y * 32 + qc];
        uu[2] = xl2[s4.z * 32 + qc];
        uu[3] = xl2[s4.w * 32 + qc];
        float4 v[4];
        float rr[4];
#pragma unroll
        for (int j = 0; j < 4; j++) {
            float2 f0 = __half22float2(*(__half2*)&uu[j].x);
            float2 f1 = __half22float2(*(__half2*)&uu[j].y);
            v[j] = make_float4(f0.x, f0.y, f1.x, f1.y);
            float e0 = v[j].x + xr4.x; e0 = fmaxf(e0, 0.2f * e0);
            float e1 = v[j].y + xr4.y; e1 = fmaxf(e1, 0.2f * e1);
            float e2 = v[j].z + xr4.z; e2 = fmaxf(e2, 0.2f * e2);
            float e3 = v[j].w + xr4.w; e3 = fmaxf(e3, 0.2f * e3);
            rr[j] = a4.x * e0 + a4.y * e1 + a4.z * e2 + a4.w * e3;
        }
#pragma unroll
        for (int j = 0; j < 4; j++) rr[j] += __shfl_xor_sync(0xffffffffu, rr[j], 1);
#pragma unroll
        for (int j = 0; j < 4; j++) rr[j] += __shfl_xor_sync(0xffffffffu, rr[j], 2);
#pragma unroll
        for (int j = 0; j < 4; j++) rr[j] += __shfl_xor_sync(0xffffffffu, rr[j], 4);
        float p0 = __expf(rr[0]);
        float p1 = __expf(rr[1]);
        float p2 = __expf(rr[2]);
        float p3 = __expf(rr[3]);
        s += p0 + p1 + p2 + p3;
        ax += p0 * v[0].x + p1 * v[1].x + p2 * v[2].x + p3 * v[3].x;
        ay += p0 * v[0].y + p1 * v[1].y + p2 * v[2].y + p3 * v[3].y;
        az += p0 * v[0].z + p1 * v[1].z + p2 * v[2].z + p3 * v[3].z;
        aw += p0 * v[0].w + p1 * v[1].w + p2 * v[2].w + p3 * v[3].w;
    }
    for (; p < end; p++) {
        int src = g_csrc[p];
        uint2 u = xl2[src * 32 + qc];
        float2 f0 = __half22float2(*(__half2*)&u.x);
        float2 f1 = __half22float2(*(__half2*)&u.y);
        float4 v = make_float4(f0.x, f0.y, f1.x, f1.y);
        float e0 = v.x + xr4.x; e0 = fmaxf(e0, 0.2f * e0);
        float e1 = v.y + xr4.y; e1 = fmaxf(e1, 0.2f * e1);
        float e2 = v.z + xr4.z; e2 = fmaxf(e2, 0.2f * e2);
        float e3 = v.w + xr4.w; e3 = fmaxf(e3, 0.2f * e3);
        float r = a4.x * e0 + a4.y * e1 + a4.z * e2 + a4.w * e3;
        r += __shfl_xor_sync(0xffffffffu, r, 1);
        r += __shfl_xor_sync(0xffffffffu, r, 2);
        r += __shfl_xor_sync(0xffffffffu, r, 4);
        float pp = __expf(r);
        s += pp;
        ax += pp * v.x; ay += pp * v.y; az += pp * v.z; aw += pp * v.w;
    }

    float inv = (s > 0.f) ? (1.f / s) : 0.f;
    float4 b4 = *(const float4*)&biasL[col];
    float o0 = fmaxf(ax * inv + b4.x, 0.f);
    float o1 = fmaxf(ay * inv + b4.y, 0.f);
    float o2 = fmaxf(az * inv + b4.z, 0.f);
    float o3 = fmaxf(aw * inv + b4.w, 0.f);
    if (add_res) {
        float4 rp = *(const float4*)&xprev[d * HID + col];
        o0 += rp.x; o1 += rp.y; o2 += rp.z; o3 += rp.w;
    }
    *(float4*)&xout[d * HID + col] = make_float4(o0, o1, o2, o3);
}

// ---------------- graph pooling ----------------
__global__ void k_reduce(const float* __restrict__ x, float* __restrict__ out) {
    int col = threadIdx.x & 127;
    int rg = threadIdx.x >> 7;
    float s = 0.f, mx = 0.f;
    for (int row = blockIdx.x * 2 + rg; row < NN; row += gridDim.x * 2) {
        float v = x[row * HID + col];
        s += v;
        mx = fmaxf(mx, v);
    }
    atomicAdd(&out[col], s);
    atomicMax((int*)&out[HID + col], __float_as_int(mx));
}
__global__ void k_scale(float* out) {
    int i = threadIdx.x;
    if (i < HID) out[i] *= (1.0f / (float)NN);
}

// ---------------- launch ----------------
extern "C" void kernel_launch(void* const* d_in, const int* in_sizes, int n_in,
                              void* d_out, int out_size) {
    const float* feat = (const float*)d_in[0];
    const int* ei = (const int*)d_in[1];
    int base = 2;
    if (n_in >= 11 || (n_in > 2 && in_sizes[2] == 1)) base = 3;
    const float* Wemb = (const float*)d_in[base + 0];
    const float* bemb = (const float*)d_in[base + 1];
    const float* Wl = (const float*)d_in[base + 2];
    const float* bl = (const float*)d_in[base + 3];
    const float* Wr = (const float*)d_in[base + 4];
    const float* br = (const float*)d_in[base + 5];
    const float* att = (const float*)d_in[base + 6];
    const float* bias = (const float*)d_in[base + 7];
    float* out = (float*)d_out;

    float *xA, *xB;
    cudaGetSymbolAddress((void**)&xA, g_xA);
    cudaGetSymbolAddress((void**)&xB, g_xB);
    __nv_bfloat16 *whi, *wlo;
    cudaGetSymbolAddress((void**)&whi, g_Wbhi);
    cudaGetSymbolAddress((void**)&wlo, g_Wblo);

    const int SMEM_GEMM = 128 * XROW * 2 * 2;
    cudaFuncSetAttribute(k_gemm_mma, cudaFuncAttributeMaxDynamicSharedMemorySize, SMEM_GEMM);

    float* xfinal = (out_size >= 256 + NN * HID) ? (out + 256) : xA;

    {
        int tot = LAYERS * 256 * HID;
        k_prep<<<(tot + 255) / 256, 256>>>(Wemb, Wl, Wr, out);
    }
    k_hist<<<(EE + 255) / 256, 256>>>(ei);
    const int NB = (NN + 255) / 256;
    k_scan1<<<NB, 256>>>();
    k_scan2<<<1, 256>>>(NB);
    k_scan3<<<NB, 256>>>();
    k_scatter<<<(EE + 255) / 256, 256>>>(ei);

    k_embed<<<(NN * HID + 255) / 256, 256>>>(feat, bemb, xA);

    const float* xin = xA;
    const int MT = (NN + 127) / 128;
    dim3 ggrid(MT, 2);
    for (int i = 0; i < LAYERS; i++) {
        k_gemm_mma<<<ggrid, 256, SMEM_GEMM>>>(xin, bl + i * HID, br + i * HID,
                                              whi + i * 256 * HID, wlo + i * 256 * HID);
        float* xo;
        if (i == 3) xo = xfinal;
        else xo = (i & 1) ? xA : xB;
        k_edge<<<(NN + 7) / 8, 256>>>(att + i * HID, bias + i * HID, xin, xo, (i > 0) ? 1 : 0);
        xin = xo;
    }

    k_reduce<<<512, 256>>>(xfinal, out);
    k_scale<<<1, 128>>>(out);
}